// round 12
// baseline (speedup 1.0000x reference)
#include <cuda_runtime.h>
#include <cuda_fp16.h>
#include <cstdint>
#include <cstddef>

// B=128, S=2048, I=256, H=512, O=256
// Two-band pipelined persistent fp16 LSTM:
//  128 CTAs = 4 band-pairs x 32 column-CTAs. Each CTA serves bands P,Q of 16
//  batch rows each (rows p*32..+15 and p*32+16..+31) and 16 h-cols x 4 gates.
//  While band Q computes, band P's barrier + h loads complete (and vice
//  versa) -> barrier/straggler/h-latency hidden behind real work.
//  Weights in registers (Breg 96/thread), mma.sync m16n8k16 f32.f16.f16.f32,
//  warp tile 16x8. Per-band 6 dedicated chunk slots (128-wide K chunks).
//  Commit order per round: c1,c2=hQ(t) c3=xP(t+1) c4,c5=hP(t+1) c6=xQ(t+1);
//  waits: x wg3, h1 wg5, h2 wg4 (both halves).
//  Sync: per-CTA monotone flags (one 128B line per band); arrive=st.cg,
//  wait=warp0 poll with nanosleep backoff, overlapped with compute.

#define TB 256
#define CHB 4352                 // bytes per chunk slot (16 rows x 272B)
#define BANDB (6 * CHB)          // 26112 per band
#define OFF_BS 0                 // 64 floats bias
#define OFF_CST 256              // 512 floats cell state (2 halves x 256)
#define OFF_CS 2304              // 16*68 floats gate preacts (4352B)
#define OFF_A 6656               // 2 bands x 6 slots
#define SMEM_BYTES (OFF_A + 2 * BANDB) // 58880

static __device__ __half g_x16[128 * 2048 * 256];
static __device__ __half g_h16[2][128 * 512];
static __device__ volatile int g_done[8 * 32]; // [band][col]

__device__ __forceinline__ void cp16(unsigned dst, const void* src) {
    asm volatile("cp.async.cg.shared.global [%0], [%1], 16;\n" ::"r"(dst), "l"(src));
}
__device__ __forceinline__ void cp_commit() { asm volatile("cp.async.commit_group;\n"); }

__device__ __forceinline__ void mma_f16(float c[4], unsigned a0, unsigned a1, unsigned a2,
                                        unsigned a3, unsigned b0, unsigned b1) {
    asm volatile(
        "mma.sync.aligned.m16n8k16.row.col.f32.f16.f16.f32 "
        "{%0,%1,%2,%3},{%4,%5,%6,%7},{%8,%9},{%0,%1,%2,%3};"
        : "+f"(c[0]), "+f"(c[1]), "+f"(c[2]), "+f"(c[3])
        : "r"(a0), "r"(a1), "r"(a2), "r"(a3), "r"(b0), "r"(b1));
}
__device__ __forceinline__ void sth(__half* p, __half v) {
    unsigned short u = __half_as_ushort(v);
    asm volatile("st.global.cg.u16 [%0], %1;" ::"l"(p), "h"(u));
}
__device__ __forceinline__ float frcp(float x) {
    float r;
    asm("rcp.approx.f32 %0, %1;" : "=f"(r) : "f"(x));
    return r;
}
__device__ __forceinline__ float fsig(float x) { return frcp(1.f + __expf(-x)); }
__device__ __forceinline__ float ftanh(float x) {
    float a = fabsf(x);
    float e = __expf(2.f * a);
    float r = 1.f - 2.f * frcp(1.f + e);
    return copysignf(r, x);
}

__global__ void __launch_bounds__(TB, 1)
lstm_persist(const float* __restrict__ W_ix, const float* __restrict__ W_fx,
             const float* __restrict__ W_ox, const float* __restrict__ W_gx,
             const float* __restrict__ W_ih, const float* __restrict__ b_ih,
             const float* __restrict__ W_fh, const float* __restrict__ b_fh,
             const float* __restrict__ W_oh, const float* __restrict__ b_oh,
             const float* __restrict__ W_gh, const float* __restrict__ b_gh) {
    extern __shared__ __align__(16) char smem[];
    float* bs = (float*)(smem + OFF_BS);
    float* cst = (float*)(smem + OFF_CST);
    float* Cs = (float*)(smem + OFF_CS);
    const unsigned sb = (unsigned)__cvta_generic_to_shared(smem);

    const int tid = threadIdx.x;
    const int cta = blockIdx.x;
    const int p = cta >> 5;
    const int col = cta & 31;
    const int hc0 = col * 16;
    const int brow[2] = {p * 32, p * 32 + 16};
    const int bnd[2] = {2 * p, 2 * p + 1};

    const int lane = tid & 31;
    const int w = tid >> 5; // 0..7, warp n-cols = w*8..w*8+7
    const int g = lane >> 2;
    const int tq = lane & 3;

    const float* Whp[4] = {W_ih, W_fh, W_oh, W_gh};
    const float* Wxp[4] = {W_ix, W_fx, W_ox, W_gx};
    const float* bbp[4] = {b_ih, b_fh, b_oh, b_gh};

    for (int i = tid; i < 64; i += TB) bs[i] = bbp[i >> 4][hc0 + (i & 15)];
    for (int i = tid; i < 512; i += TB) cst[i] = 0.f;

    // ---- Hoist B fragments to registers (96/thread), staged via A area.
    unsigned Breg[6][8][2];
    {
        __half* Wt = (__half*)(smem + OFF_A);
        const unsigned* Wu = (const unsigned*)(smem + OFF_A);
#pragma unroll
        for (int kc = 0; kc < 6; ++kc) {
            __syncthreads();
            for (int idx = tid; idx < 64 * 128; idx += TB) {
                int n = idx >> 7;
                int kl = idx & 127;
                int k = kc * 128 + kl;
                int gate = n >> 4;
                int hc = hc0 + (n & 15);
                float v = (k < 256) ? Wxp[gate][hc * 256 + k]
                                    : Whp[gate][hc * 512 + (k - 256)];
                Wt[n * 136 + kl] = __float2half_rn(v);
            }
            __syncthreads();
#pragma unroll
            for (int kk = 0; kk < 8; ++kk) {
                int wn = (w * 8 + g) * 68 + kk * 8 + tq;
                Breg[kc][kk][0] = Wu[wn];
                Breg[kc][kk][1] = Wu[wn + 4];
            }
        }
        __syncthreads();
    }

    // ---- Staging thread mapping: one chunk = 16 rows x 16 x 16B = 256 slots.
    const int srow = tid >> 4; // 0..15
    const int sq = tid & 15;   // 0..15
    const unsigned dB0 = (unsigned)srow * 272 + (unsigned)sq * 16;
    const size_t xoff[2] = {((size_t)(brow[0] + srow) * 2048) * 256,
                            ((size_t)(brow[1] + srow) * 2048) * 256};
    const size_t hoff[2] = {(size_t)(brow[0] + srow) * 512,
                            (size_t)(brow[1] + srow) * 512};

    // issue x chunks 0,1 of band X for step sti (2 cp16/thread); caller commits
    auto issue_x = [&](int X, int sti) {
        if (sti < 2048) {
            unsigned d = sb + OFF_A + (unsigned)X * BANDB + dB0;
            const __half* s = g_x16 + xoff[X] + (size_t)sti * 256 + sq * 8;
            cp16(d, s);            // chunk 0: cols [0,128)
            cp16(d + CHB, s + 128); // chunk 1: cols [128,256)
        }
    };
    // issue h chunks 2+2*pi, 3+2*pi of band X for step sti
    auto issue_h = [&](int X, int sti, int pi) {
        unsigned d = sb + OFF_A + (unsigned)X * BANDB + (unsigned)(2 + 2 * pi) * CHB + dB0;
        const __half* s = g_h16[sti & 1] + hoff[X] + pi * 256 + sq * 8;
        cp16(d, s);
        cp16(d + CHB, s + 128);
    };

    // ---- Prime: xP(0) [c3], hP(0)p0 [c4], hP(0)p1 [c5], xQ(0) [c6]
    issue_x(0, 0); cp_commit();
    issue_h(0, 0, 0); cp_commit();
    issue_h(0, 0, 1); cp_commit();
    issue_x(1, 0); cp_commit();

    for (int t = 0; t < 2048; ++t) {
#pragma unroll
        for (int hf = 0; hf < 2; ++hf) {
            const int other = hf ^ 1;
            const int tgt = t + hf; // hf=0: need hQ(t); hf=1: need hP(t+1)
            float acc[4] = {0.f, 0.f, 0.f, 0.f};
            const unsigned* Ab =
                (const unsigned*)(smem + OFF_A + hf * BANDB);

            // -- consume x chunks 0,1
            asm volatile("cp.async.wait_group 3;\n" ::: "memory");
            __syncthreads();
#pragma unroll
            for (int kc = 0; kc < 2; ++kc)
#pragma unroll
                for (int kk = 0; kk < 8; ++kk) {
                    const unsigned* Au = Ab + kc * (CHB / 4);
                    int kb = kk * 8 + tq;
                    unsigned a0 = Au[g * 68 + kb];
                    unsigned a1 = Au[(g + 8) * 68 + kb];
                    unsigned a2 = Au[g * 68 + kb + 4];
                    unsigned a3 = Au[(g + 8) * 68 + kb + 4];
                    mma_f16(acc, a0, a1, a2, a3, Breg[kc][kk][0], Breg[kc][kk][1]);
                }

            // -- wait other band's h ready (warp0 poll, backoff), then issue
            if (w == 0) {
                const volatile int* fl = &g_done[bnd[other] * 32];
                while (true) {
                    int v = fl[lane];
                    if (__all_sync(0xffffffffu, v >= tgt)) break;
                    __nanosleep(32);
                }
                asm volatile("fence.acq_rel.gpu;" ::: "memory");
            }
            __syncthreads();
            issue_h(other, tgt, 0); cp_commit(); // c1 / c4
            issue_h(other, tgt, 1); cp_commit(); // c2 / c5
            issue_x(hf, t + 1); cp_commit();     // c3 / c6

            // -- consume h chunks 2,3 then 4,5
            asm volatile("cp.async.wait_group 5;\n" ::: "memory");
            __syncthreads();
#pragma unroll
            for (int kc = 2; kc < 4; ++kc)
#pragma unroll
                for (int kk = 0; kk < 8; ++kk) {
                    const unsigned* Au = Ab + kc * (CHB / 4);
                    int kb = kk * 8 + tq;
                    unsigned a0 = Au[g * 68 + kb];
                    unsigned a1 = Au[(g + 8) * 68 + kb];
                    unsigned a2 = Au[g * 68 + kb + 4];
                    unsigned a3 = Au[(g + 8) * 68 + kb + 4];
                    mma_f16(acc, a0, a1, a2, a3, Breg[kc][kk][0], Breg[kc][kk][1]);
                }
            asm volatile("cp.async.wait_group 4;\n" ::: "memory");
            __syncthreads();
#pragma unroll
            for (int kc = 4; kc < 6; ++kc)
#pragma unroll
                for (int kk = 0; kk < 8; ++kk) {
                    const unsigned* Au = Ab + kc * (CHB / 4);
                    int kb = kk * 8 + tq;
                    unsigned a0 = Au[g * 68 + kb];
                    unsigned a1 = Au[(g + 8) * 68 + kb];
                    unsigned a2 = Au[g * 68 + kb + 4];
                    unsigned a3 = Au[(g + 8) * 68 + kb + 4];
                    mma_f16(acc, a0, a1, a2, a3, Breg[kc][kk][0], Breg[kc][kk][1]);
                }

            // -- gate preactivations to Cs (16 rows x 64 cols)
            {
                int c0 = w * 8 + 2 * tq;
                Cs[g * 68 + c0] = acc[0];
                Cs[g * 68 + c0 + 1] = acc[1];
                Cs[(g + 8) * 68 + c0] = acc[2];
                Cs[(g + 8) * 68 + c0 + 1] = acc[3];
            }
            __syncthreads();

            // -- epilogue: 256 cells, 1/thread
            {
                int rr = tid >> 4, hc = tid & 15;
                const float* Crow = Cs + rr * 68;
                float zi = Crow[hc] + bs[hc];
                float zf = Crow[16 + hc] + bs[16 + hc];
                float zo = Crow[32 + hc] + bs[32 + hc];
                float zg = Crow[48 + hc] + bs[48 + hc];
                float cprev = cst[hf * 256 + tid];
                float c = ftanh(zg) * fsig(zi) + cprev * fsig(zf);
                cst[hf * 256 + tid] = c;
                float h = ftanh(c) * fsig(zo);
                sth(&g_h16[(t + 1) & 1][(size_t)(brow[hf] + rr) * 512 + hc0 + hc],
                    __float2half_rn(h));
            }
            __syncthreads(); // all h stores issued before release

            // -- arrive: monotone per-CTA flag (non-blocking st.cg path)
            if (tid == 0) {
                asm volatile("fence.acq_rel.gpu;" ::: "memory");
                g_done[bnd[hf] * 32 + col] = t + 1;
            }
        }
    }
    asm volatile("cp.async.wait_group 0;\n" ::: "memory");
    __syncthreads();
}

__global__ void cvt_x(const float* __restrict__ x) {
    size_t n2 = (size_t)128 * 2048 * 256 / 2;
    size_t stride = (size_t)gridDim.x * blockDim.x;
    for (size_t i = (size_t)blockIdx.x * blockDim.x + threadIdx.x; i < n2; i += stride) {
        float2 v = ((const float2*)x)[i];
        ((__half2*)g_x16)[i] = __floats2half2_rn(v.x, v.y);
    }
}

__global__ void init_k() {
    int i = blockIdx.x * blockDim.x + threadIdx.x;
    if (i < 8 * 32) g_done[i] = 0;
    for (int j = i; j < 128 * 512 / 2; j += gridDim.x * blockDim.x)
        ((__half2*)g_h16[0])[j] = __floats2half2_rn(0.f, 0.f);
}

// out[b][o] = h_final[b] . W_ph[o] + b_ph[o]; h_final = g_h16[0] (2048 even)
__global__ void __launch_bounds__(256) proj_k(const float* __restrict__ W_ph,
                                              const float* __restrict__ b_ph,
                                              float* __restrict__ out) {
    __shared__ float hs[512];
    int b = blockIdx.x;
    const __half* hrow = g_h16[0] + (size_t)b * 512;
    for (int i = threadIdx.x; i < 512; i += 256) hs[i] = __half2float(hrow[i]);
    __syncthreads();
    int o = threadIdx.x;
    const float* wr = W_ph + o * 512;
    float acc = b_ph[o];
#pragma unroll 8
    for (int k = 0; k < 512; ++k) acc += hs[k] * wr[k];
    out[b * 256 + o] = acc;
}

extern "C" void kernel_launch(void* const* d_in, const int* in_sizes, int n_in,
                              void* d_out, int out_size) {
    (void)in_sizes; (void)n_in; (void)out_size;
    const float* x    = (const float*)d_in[0];
    const float* W_ix = (const float*)d_in[1];
    const float* W_fx = (const float*)d_in[2];
    const float* W_ox = (const float*)d_in[3];
    const float* W_gx = (const float*)d_in[4];
    const float* W_ih = (const float*)d_in[5];
    const float* b_ih = (const float*)d_in[6];
    const float* W_fh = (const float*)d_in[7];
    const float* b_fh = (const float*)d_in[8];
    const float* W_oh = (const float*)d_in[9];
    const float* b_oh = (const float*)d_in[10];
    const float* W_gh = (const float*)d_in[11];
    const float* b_gh = (const float*)d_in[12];
    const float* W_ph = (const float*)d_in[13];
    const float* b_ph = (const float*)d_in[14];

    cudaFuncSetAttribute(lstm_persist, cudaFuncAttributeMaxDynamicSharedMemorySize, SMEM_BYTES);

    cvt_x<<<2048, 256>>>(x);
    init_k<<<256, 256>>>();
    lstm_persist<<<128, TB, SMEM_BYTES>>>(W_ix, W_fx, W_ox, W_gx,
                                          W_ih, b_ih, W_fh, b_fh, W_oh, b_oh, W_gh, b_gh);
    proj_k<<<128, 256>>>(W_ph, b_ph, (float*)d_out);
}

// round 13
// speedup vs baseline: 1.2643x; 1.2643x over previous
#include <cuda_runtime.h>
#include <cuda_fp16.h>
#include <cstdint>
#include <cstddef>

// B=128, S=2048, I=256, H=512, O=256
// SINGLE-KERNEL persistent fp16 LSTM (R8 core verbatim), merged phases:
//  phase0: grid-stride x fp32->fp16 + zero h(0)
//  entry barrier: generation counter, resets band flags (replay-safe)
//  mainloop: R8 exactly -- weights-in-registers (Breg 192 b32/thread),
//   mma.sync m16n8k16 f32.f16.f16.f32, 128-wide K chunks (6/step), 3-slot
//   cp.async ring depth-2, smem Cs/cst epilogue, atomic-chain band barrier.
//  tail: per-CTA output projection for row band*32+col.
// One launch per call => ncu -s 5 -c 1 must capture THIS kernel.

#define TB 256
#define NCTA 128
#define ASTR 68                   // b32 per A row (136 halves)
#define ASLOT_B (32 * ASTR * 4)   // 8704 B per ring slot
#define OFF_BS 0                  // 64 floats bias
#define OFF_CST 256               // 512 floats cell state
#define OFF_CS 2304               // 32*68 floats gate preacts
#define OFF_A 11008               // ring: 3 slots (also staging/proj scratch)
#define SMEM_BYTES (OFF_A + 3 * ASLOT_B) // 37120

static __device__ __half g_x16[128 * 2048 * 256];
static __device__ __half g_h16[2][128 * 512];
static __device__ int g_cnt[128];
static __device__ volatile int g_flag[128];
static __device__ int g_arr;
static __device__ volatile int g_gen;

__device__ __forceinline__ void cp16(unsigned dst, const void* src) {
    asm volatile("cp.async.cg.shared.global [%0], [%1], 16;\n" ::"r"(dst), "l"(src));
}
__device__ __forceinline__ void cp_commit() { asm volatile("cp.async.commit_group;\n"); }
__device__ __forceinline__ void cp_wait1() { asm volatile("cp.async.wait_group 1;\n"); }

__device__ __forceinline__ void mma_f16(float c[4], unsigned a0, unsigned a1, unsigned a2,
                                        unsigned a3, unsigned b0, unsigned b1) {
    asm volatile(
        "mma.sync.aligned.m16n8k16.row.col.f32.f16.f16.f32 "
        "{%0,%1,%2,%3},{%4,%5,%6,%7},{%8,%9},{%0,%1,%2,%3};"
        : "+f"(c[0]), "+f"(c[1]), "+f"(c[2]), "+f"(c[3])
        : "r"(a0), "r"(a1), "r"(a2), "r"(a3), "r"(b0), "r"(b1));
}
__device__ __forceinline__ void sth(__half* p, __half v) {
    unsigned short u = __half_as_ushort(v);
    asm volatile("st.global.cg.u16 [%0], %1;" ::"l"(p), "h"(u));
}
__device__ __forceinline__ float fsig(float x) { return 1.f / (1.f + __expf(-x)); }
__device__ __forceinline__ float ftanh(float x) {
    float a = fabsf(x);
    float e = __expf(2.f * a);
    float r = 1.f - 2.f / (1.f + e);
    return copysignf(r, x);
}

__global__ void __launch_bounds__(TB, 1)
lstm_all(const float* __restrict__ x,
         const float* __restrict__ W_ix, const float* __restrict__ W_fx,
         const float* __restrict__ W_ox, const float* __restrict__ W_gx,
         const float* __restrict__ W_ih, const float* __restrict__ b_ih,
         const float* __restrict__ W_fh, const float* __restrict__ b_fh,
         const float* __restrict__ W_oh, const float* __restrict__ b_oh,
         const float* __restrict__ W_gh, const float* __restrict__ b_gh,
         const float* __restrict__ W_ph, const float* __restrict__ b_ph,
         float* __restrict__ out) {
    extern __shared__ __align__(16) char smem[];
    float* bs = (float*)(smem + OFF_BS);
    float* cst = (float*)(smem + OFF_CST);
    float* Cs = (float*)(smem + OFF_CS);
    const unsigned sb = (unsigned)__cvta_generic_to_shared(smem);

    const int tid = threadIdx.x;
    const int cta = blockIdx.x;
    const int band = cta >> 5;
    const int col = cta & 31;
    const int hc0 = col * 16;
    const int brow0 = band * 32;

    const int lane = tid & 31;
    const int w = tid >> 5;
    const int g = lane >> 2;
    const int tq = lane & 3;
    const int wr0 = (w & 1) * 16;  // warp row base (0/16)
    const int wc0 = (w >> 1) * 16; // warp col base (0/16/32/48)

    // ================= PHASE 0: x -> fp16, zero h(0) =================
    {
        const size_t n2 = (size_t)128 * 2048 * 256 / 2;
        for (size_t i = (size_t)cta * TB + tid; i < n2; i += (size_t)NCTA * TB) {
            float2 v = ((const float2*)x)[i];
            ((__half2*)g_x16)[i] = __floats2half2_rn(v.x, v.y);
        }
        for (int j = cta * TB + tid; j < 128 * 512 / 2; j += NCTA * TB)
            ((__half2*)g_h16[0])[j] = __floats2half2_rn(0.f, 0.f);
    }

    const float* Whp[4] = {W_ih, W_fh, W_oh, W_gh};
    const float* Wxp[4] = {W_ix, W_fx, W_ox, W_gx};
    const float* bbp[4] = {b_ih, b_fh, b_oh, b_gh};

    for (int i = tid; i < 64; i += TB) bs[i] = bbp[i >> 4][hc0 + (i & 15)];
    for (int i = tid; i < 512; i += TB) cst[i] = 0.f;

    // ---- Hoist B fragments into registers (R8 verbatim), staged via A ring.
    unsigned Breg[6][8][2][2];
    {
        __half* Wt = (__half*)(smem + OFF_A);
        const unsigned* Wu = (const unsigned*)(smem + OFF_A);
#pragma unroll
        for (int kc = 0; kc < 6; ++kc) {
            __syncthreads();
            for (int idx = tid; idx < 64 * 128; idx += TB) {
                int n = idx >> 7;
                int kl = idx & 127;
                int k = kc * 128 + kl;
                int gate = n >> 4;
                int hc = hc0 + (n & 15);
                float v = (k < 256) ? Wxp[gate][hc * 256 + k]
                                    : Whp[gate][hc * 512 + (k - 256)];
                Wt[n * 136 + kl] = __float2half_rn(v);
            }
            __syncthreads();
#pragma unroll
            for (int kk = 0; kk < 8; ++kk)
#pragma unroll
                for (int nt = 0; nt < 2; ++nt) {
                    int wn = (wc0 + nt * 8 + g) * ASTR + kk * 8 + tq;
                    Breg[kc][kk][nt][0] = Wu[wn];
                    Breg[kc][kk][nt][1] = Wu[wn + 4];
                }
        }
        __syncthreads();
    }

    // ================= ENTRY BARRIER (generation counter, replay-safe) ====
    // All CTAs finished phase 0; last arriver resets the 4 band flags.
    if (tid == 0) {
        int G = g_gen;
        asm volatile("fence.acq_rel.gpu;" ::: "memory");
        int old = atomicAdd(&g_arr, 1);
        if (old == NCTA - 1) {
            g_flag[0] = 0; g_flag[32] = 0; g_flag[64] = 0; g_flag[96] = 0;
            atomicExch(&g_arr, 0);
            asm volatile("fence.acq_rel.gpu;" ::: "memory");
            g_gen = G + 1;
        } else {
            while (g_gen == G) { __nanosleep(64); }
            asm volatile("fence.acq_rel.gpu;" ::: "memory");
        }
    }
    __syncthreads();

    // ================= MAINLOOP (R8 verbatim) =================
    const int ar = tid >> 3; // 0..31 row
    const int aq = tid & 7;  // 0..7
    const unsigned dA0 = (unsigned)ar * 272 + (unsigned)aq * 16;
    const size_t xrow = ((size_t)(brow0 + ar) * 2048) * 256;
    const size_t hrow = (size_t)(brow0 + ar) * 512;

    auto issue_x = [&](int sti, int ci, int slot) {
        if (sti >= 2048) return;
        unsigned d = sb + OFF_A + (unsigned)slot * ASLOT_B + dA0;
        const __half* s = g_x16 + xrow + (size_t)sti * 256 + ci * 128 + aq * 8;
        cp16(d, s);
        cp16(d + 128, s + 64);
    };
    auto issue_h = [&](int sti, int ci, int slot) {
        unsigned d = sb + OFF_A + (unsigned)slot * ASLOT_B + dA0;
        const __half* s = g_h16[sti & 1] + hrow + (ci - 2) * 128 + aq * 8;
        cp16(d, s);
        cp16(d + 128, s + 64);
    };

    issue_x(0, 0, 0); cp_commit();
    issue_x(0, 1, 1); cp_commit();

    for (int ti = 0; ti < 2048; ++ti) {
        float acc[2][4];
#pragma unroll
        for (int n = 0; n < 2; n++)
#pragma unroll
            for (int j = 0; j < 4; j++) acc[n][j] = 0.f;

#pragma unroll
        for (int kc = 0; kc < 6; ++kc) {
            cp_wait1();
            __syncthreads();
            if (kc < 4) issue_h(ti, kc + 2, (kc + 2) % 3);
            else        issue_x(ti + 1, kc - 4, (kc + 2) % 3);
            cp_commit();

            const unsigned* Au = (const unsigned*)(smem + OFF_A + (kc % 3) * ASLOT_B);
#pragma unroll
            for (int kk = 0; kk < 8; ++kk) {
                int kb = kk * 8 + tq;
                unsigned a0 = Au[(wr0 + g) * ASTR + kb];
                unsigned a1 = Au[(wr0 + g + 8) * ASTR + kb];
                unsigned a2 = Au[(wr0 + g) * ASTR + kb + 4];
                unsigned a3 = Au[(wr0 + g + 8) * ASTR + kb + 4];
                mma_f16(acc[0], a0, a1, a2, a3, Breg[kc][kk][0][0], Breg[kc][kk][0][1]);
                mma_f16(acc[1], a0, a1, a2, a3, Breg[kc][kk][1][0], Breg[kc][kk][1][1]);
            }
        }

        __syncthreads();
#pragma unroll
        for (int nt = 0; nt < 2; ++nt) {
            int c0 = wc0 + nt * 8 + 2 * tq;
            Cs[(wr0 + g) * 68 + c0] = acc[nt][0];
            Cs[(wr0 + g) * 68 + c0 + 1] = acc[nt][1];
            Cs[(wr0 + g + 8) * 68 + c0] = acc[nt][2];
            Cs[(wr0 + g + 8) * 68 + c0 + 1] = acc[nt][3];
        }
        __syncthreads();

        __half* hcur = g_h16[(ti + 1) & 1];
        for (int it = tid; it < 512; it += TB) {
            int r = it >> 4, hc = it & 15;
            const float* Crow = Cs + r * 68;
            float zi = Crow[hc] + bs[hc];
            float zf = Crow[16 + hc] + bs[16 + hc];
            float zo = Crow[32 + hc] + bs[32 + hc];
            float zg = Crow[48 + hc] + bs[48 + hc];
            float gi_ = fsig(zi);
            float gf = fsig(zf);
            float go = fsig(zo);
            float gg = ftanh(zg);
            float c = gg * gi_ + cst[it] * gf;
            cst[it] = c;
            float h = ftanh(c) * go;
            sth(&hcur[(size_t)(brow0 + r) * 512 + hc0 + hc], __float2half_rn(h));
        }
        __syncthreads();

        if (tid == 0) {
            asm volatile("fence.acq_rel.gpu;" ::: "memory");
            int prev = atomicAdd(&g_cnt[band * 32], 1);
            if (prev == 31) {
                atomicExch(&g_cnt[band * 32], 0);
                g_flag[band * 32] = ti + 1;
            } else {
                while (g_flag[band * 32] < ti + 1) { __nanosleep(64); }
                asm volatile("fence.acq_rel.gpu;" ::: "memory");
            }
        }
        __syncthreads();
    }

    // ================= TAIL: projection for row brow0+col =================
    asm volatile("cp.async.wait_group 0;\n" ::: "memory");
    __syncthreads(); // A ring quiescent -> reuse as h scratch
    {
        float* hsp = (float*)(smem + OFF_A);
        const int row = brow0 + col; // rows covered exactly once across CTAs
        const __half* hr = g_h16[0] + (size_t)row * 512; // h(2048), 2048 even
        for (int i = tid; i < 512; i += TB) hsp[i] = __half2float(hr[i]);
        __syncthreads();
        int o = tid;
        const float* wr = W_ph + o * 512;
        float acc = b_ph[o];
#pragma unroll 8
        for (int k = 0; k < 512; ++k) acc += hsp[k] * wr[k];
        out[row * 256 + o] = acc;
    }
}

extern "C" void kernel_launch(void* const* d_in, const int* in_sizes, int n_in,
                              void* d_out, int out_size) {
    (void)in_sizes; (void)n_in; (void)out_size;
    const float* x    = (const float*)d_in[0];
    const float* W_ix = (const float*)d_in[1];
    const float* W_fx = (const float*)d_in[2];
    const float* W_ox = (const float*)d_in[3];
    const float* W_gx = (const float*)d_in[4];
    const float* W_ih = (const float*)d_in[5];
    const float* b_ih = (const float*)d_in[6];
    const float* W_fh = (const float*)d_in[7];
    const float* b_fh = (const float*)d_in[8];
    const float* W_oh = (const float*)d_in[9];
    const float* b_oh = (const float*)d_in[10];
    const float* W_gh = (const float*)d_in[11];
    const float* b_gh = (const float*)d_in[12];
    const float* W_ph = (const float*)d_in[13];
    const float* b_ph = (const float*)d_in[14];

    cudaFuncSetAttribute(lstm_all, cudaFuncAttributeMaxDynamicSharedMemorySize, SMEM_BYTES);
    lstm_all<<<NCTA, TB, SMEM_BYTES>>>(x, W_ix, W_fx, W_ox, W_gx,
                                       W_ih, b_ih, W_fh, b_fh, W_oh, b_oh, W_gh, b_gh,
                                       W_ph, b_ph, (float*)d_out);
}

// round 16
// speedup vs baseline: 1.4829x; 1.1728x over previous
#include <cuda_runtime.h>
#include <cuda_fp16.h>
#include <cstdint>
#include <cstddef>

// B=128, S=2048, I=256, H=512, O=256
// SINGLE-KERNEL persistent fp16 LSTM (R8 core), R14 work cuts:
//  - A operand via ldmatrix.m8n8.x4 (1 instr per k-step vs 4 LDS.b32)
//  - epilogue divides via rcp.approx (no IEEE div chains; R12-validated)
//  - one redundant __syncthreads removed
// Everything else (ring, barrier protocol, epilogue structure) R8-verbatim.

#define TB 256
#define NCTA 128
#define ASTR 68                   // b32 per A row (136 halves); row stride 272B
#define ASLOT_B (32 * ASTR * 4)   // 8704 B per ring slot
#define OFF_BS 0                  // 64 floats bias
#define OFF_CST 256               // 512 floats cell state
#define OFF_CS 2304               // 32*68 floats gate preacts
#define OFF_A 11008               // ring: 3 slots (also staging/proj scratch)
#define SMEM_BYTES (OFF_A + 3 * ASLOT_B) // 37120

static __device__ __half g_x16[128 * 2048 * 256];
static __device__ __half g_h16[2][128 * 512];
static __device__ int g_cnt[128];
static __device__ volatile int g_flag[128];
static __device__ int g_arr;
static __device__ volatile int g_gen;

__device__ __forceinline__ void cp16(unsigned dst, const void* src) {
    asm volatile("cp.async.cg.shared.global [%0], [%1], 16;\n" ::"r"(dst), "l"(src));
}
__device__ __forceinline__ void cp_commit() { asm volatile("cp.async.commit_group;\n"); }
__device__ __forceinline__ void cp_wait1() { asm volatile("cp.async.wait_group 1;\n"); }

__device__ __forceinline__ void mma_f16(float c[4], unsigned a0, unsigned a1, unsigned a2,
                                        unsigned a3, unsigned b0, unsigned b1) {
    asm volatile(
        "mma.sync.aligned.m16n8k16.row.col.f32.f16.f16.f32 "
        "{%0,%1,%2,%3},{%4,%5,%6,%7},{%8,%9},{%0,%1,%2,%3};"
        : "+f"(c[0]), "+f"(c[1]), "+f"(c[2]), "+f"(c[3])
        : "r"(a0), "r"(a1), "r"(a2), "r"(a3), "r"(b0), "r"(b1));
}
__device__ __forceinline__ void sth(__half* p, __half v) {
    unsigned short u = __half_as_ushort(v);
    asm volatile("st.global.cg.u16 [%0], %1;" ::"l"(p), "h"(u));
}
__device__ __forceinline__ float frcp(float x) {
    float r;
    asm("rcp.approx.f32 %0, %1;" : "=f"(r) : "f"(x));
    return r;
}
__device__ __forceinline__ float fsig(float x) { return frcp(1.f + __expf(-x)); }
__device__ __forceinline__ float ftanh(float x) {
    float a = fabsf(x);
    float e = __expf(2.f * a);
    float r = 1.f - 2.f * frcp(1.f + e);
    return copysignf(r, x);
}

__global__ void __launch_bounds__(TB, 1)
lstm_all(const float* __restrict__ x,
         const float* __restrict__ W_ix, const float* __restrict__ W_fx,
         const float* __restrict__ W_ox, const float* __restrict__ W_gx,
         const float* __restrict__ W_ih, const float* __restrict__ b_ih,
         const float* __restrict__ W_fh, const float* __restrict__ b_fh,
         const float* __restrict__ W_oh, const float* __restrict__ b_oh,
         const float* __restrict__ W_gh, const float* __restrict__ b_gh,
         const float* __restrict__ W_ph, const float* __restrict__ b_ph,
         float* __restrict__ out) {
    extern __shared__ __align__(16) char smem[];
    float* bs = (float*)(smem + OFF_BS);
    float* cst = (float*)(smem + OFF_CST);
    float* Cs = (float*)(smem + OFF_CS);
    const unsigned sb = (unsigned)__cvta_generic_to_shared(smem);

    const int tid = threadIdx.x;
    const int cta = blockIdx.x;
    const int band = cta >> 5;
    const int col = cta & 31;
    const int hc0 = col * 16;
    const int brow0 = band * 32;

    const int lane = tid & 31;
    const int w = tid >> 5;
    const int g = lane >> 2;
    const int tq = lane & 3;
    const int wr0 = (w & 1) * 16;  // warp row base (0/16)
    const int wc0 = (w >> 1) * 16; // warp col base (0/16/32/48)

    // ================= PHASE 0: x -> fp16, zero h(0) =================
    {
        const size_t n2 = (size_t)128 * 2048 * 256 / 2;
        for (size_t i = (size_t)cta * TB + tid; i < n2; i += (size_t)NCTA * TB) {
            float2 v = ((const float2*)x)[i];
            ((__half2*)g_x16)[i] = __floats2half2_rn(v.x, v.y);
        }
        for (int j = cta * TB + tid; j < 128 * 512 / 2; j += NCTA * TB)
            ((__half2*)g_h16[0])[j] = __floats2half2_rn(0.f, 0.f);
    }

    const float* Whp[4] = {W_ih, W_fh, W_oh, W_gh};
    const float* Wxp[4] = {W_ix, W_fx, W_ox, W_gx};
    const float* bbp[4] = {b_ih, b_fh, b_oh, b_gh};

    for (int i = tid; i < 64; i += TB) bs[i] = bbp[i >> 4][hc0 + (i & 15)];
    for (int i = tid; i < 512; i += TB) cst[i] = 0.f;

    // ---- Hoist B fragments into registers (R8 verbatim), staged via A ring.
    unsigned Breg[6][8][2][2];
    {
        __half* Wt = (__half*)(smem + OFF_A);
        const unsigned* Wu = (const unsigned*)(smem + OFF_A);
#pragma unroll
        for (int kc = 0; kc < 6; ++kc) {
            __syncthreads();
            for (int idx = tid; idx < 64 * 128; idx += TB) {
                int n = idx >> 7;
                int kl = idx & 127;
                int k = kc * 128 + kl;
                int gate = n >> 4;
                int hc = hc0 + (n & 15);
                float v = (k < 256) ? Wxp[gate][hc * 256 + k]
                                    : Whp[gate][hc * 512 + (k - 256)];
                Wt[n * 136 + kl] = __float2half_rn(v);
            }
            __syncthreads();
#pragma unroll
            for (int kk = 0; kk < 8; ++kk)
#pragma unroll
                for (int nt = 0; nt < 2; ++nt) {
                    int wn = (wc0 + nt * 8 + g) * ASTR + kk * 8 + tq;
                    Breg[kc][kk][nt][0] = Wu[wn];
                    Breg[kc][kk][nt][1] = Wu[wn + 4];
                }
        }
        __syncthreads();
    }

    // ================= ENTRY BARRIER (generation counter, replay-safe) ====
    if (tid == 0) {
        int G = g_gen;
        asm volatile("fence.acq_rel.gpu;" ::: "memory");
        int old = atomicAdd(&g_arr, 1);
        if (old == NCTA - 1) {
            g_flag[0] = 0; g_flag[32] = 0; g_flag[64] = 0; g_flag[96] = 0;
            atomicExch(&g_arr, 0);
            asm volatile("fence.acq_rel.gpu;" ::: "memory");
            g_gen = G + 1;
        } else {
            while (g_gen == G) { __nanosleep(64); }
            asm volatile("fence.acq_rel.gpu;" ::: "memory");
        }
    }
    __syncthreads();

    // ================= MAINLOOP (R8 core + ldmatrix A) =================
    const int ar = tid >> 3; // 0..31 row
    const int aq = tid & 7;  // 0..7
    const unsigned dA0 = (unsigned)ar * 272 + (unsigned)aq * 16;
    const size_t xrow = ((size_t)(brow0 + ar) * 2048) * 256;
    const size_t hrow = (size_t)(brow0 + ar) * 512;

    // ldmatrix per-lane address offset: lanes 0-7 rows wr0+0..7 (k low 16B),
    // 8-15 rows wr0+8..15, 16-23 rows wr0+0..7 (+16B), 24-31 rows +8 (+16B).
    const unsigned a_off =
        (unsigned)((wr0 + (lane & 15)) * 272 + ((lane >> 4) & 1) * 16);

    auto issue_x = [&](int sti, int ci, int slot) {
        if (sti >= 2048) return;
        unsigned d = sb + OFF_A + (unsigned)slot * ASLOT_B + dA0;
        const __half* s = g_x16 + xrow + (size_t)sti * 256 + ci * 128 + aq * 8;
        cp16(d, s);
        cp16(d + 128, s + 64);
    };
    auto issue_h = [&](int sti, int ci, int slot) {
        unsigned d = sb + OFF_A + (unsigned)slot * ASLOT_B + dA0;
        const __half* s = g_h16[sti & 1] + hrow + (ci - 2) * 128 + aq * 8;
        cp16(d, s);
        cp16(d + 128, s + 64);
    };

    issue_x(0, 0, 0); cp_commit();
    issue_x(0, 1, 1); cp_commit();

    for (int ti = 0; ti < 2048; ++ti) {
        float acc[2][4];
#pragma unroll
        for (int n = 0; n < 2; n++)
#pragma unroll
            for (int j = 0; j < 4; j++) acc[n][j] = 0.f;

#pragma unroll
        for (int kc = 0; kc < 6; ++kc) {
            cp_wait1();
            __syncthreads();
            if (kc < 4) issue_h(ti, kc + 2, (kc + 2) % 3);
            else        issue_x(ti + 1, kc - 4, (kc + 2) % 3);
            cp_commit();

            const unsigned abase = sb + OFF_A + (unsigned)((kc % 3) * ASLOT_B) + a_off;
#pragma unroll
            for (int kk = 0; kk < 8; ++kk) {
                unsigned a0, a1, a2, a3;
                asm volatile(
                    "ldmatrix.sync.aligned.m8n8.x4.shared.b16 {%0,%1,%2,%3}, [%4];"
                    : "=r"(a0), "=r"(a1), "=r"(a2), "=r"(a3)
                    : "r"(abase + (unsigned)(kk * 32)));
                mma_f16(acc[0], a0, a1, a2, a3, Breg[kc][kk][0][0], Breg[kc][kk][0][1]);
                mma_f16(acc[1], a0, a1, a2, a3, Breg[kc][kk][1][0], Breg[kc][kk][1][1]);
            }
        }

        // ---- Gate preactivations to Cs (no extra bar: Cs is dedicated; the
        // band-barrier bar of step ti-1 ordered the previous epilogue reads)
#pragma unroll
        for (int nt = 0; nt < 2; ++nt) {
            int c0 = wc0 + nt * 8 + 2 * tq;
            Cs[(wr0 + g) * 68 + c0] = acc[nt][0];
            Cs[(wr0 + g) * 68 + c0 + 1] = acc[nt][1];
            Cs[(wr0 + g + 8) * 68 + c0] = acc[nt][2];
            Cs[(wr0 + g + 8) * 68 + c0 + 1] = acc[nt][3];
        }
        __syncthreads();

        // ---- Cell update (fp32, rcp.approx), h store (fp16, st.cg -> L2)
        __half* hcur = g_h16[(ti + 1) & 1];
        for (int it = tid; it < 512; it += TB) {
            int r = it >> 4, hc = it & 15;
            const float* Crow = Cs + r * 68;
            float zi = Crow[hc] + bs[hc];
            float zf = Crow[16 + hc] + bs[16 + hc];
            float zo = Crow[32 + hc] + bs[32 + hc];
            float zg = Crow[48 + hc] + bs[48 + hc];
            float gi_ = fsig(zi);
            float gf = fsig(zf);
            float go = fsig(zo);
            float gg = ftanh(zg);
            float c = gg * gi_ + cst[it] * gf;
            cst[it] = c;
            float h = ftanh(c) * go;
            sth(&hcur[(size_t)(brow0 + r) * 512 + hc0 + hc], __float2half_rn(h));
        }
        __syncthreads();

        // ---- Band barrier: proven atomic chain + nanosleep (DO NOT TOUCH)
        if (tid == 0) {
            asm volatile("fence.acq_rel.gpu;" ::: "memory");
            int prev = atomicAdd(&g_cnt[band * 32], 1);
            if (prev == 31) {
                atomicExch(&g_cnt[band * 32], 0);
                g_flag[band * 32] = ti + 1;
            } else {
                while (g_flag[band * 32] < ti + 1) { __nanosleep(64); }
                asm volatile("fence.acq_rel.gpu;" ::: "memory");
            }
        }
        __syncthreads();
    }

    // ================= TAIL: projection for row brow0+col =================
    asm volatile("cp.async.wait_group 0;\n" ::: "memory");
    __syncthreads(); // A ring quiescent -> reuse as h scratch
    {
        float* hsp = (float*)(smem + OFF_A);
        const int row = brow0 + col;
        const __half* hr = g_h16[0] + (size_t)row * 512; // h(2048), 2048 even
        for (int i = tid; i < 512; i += TB) hsp[i] = __half2float(hr[i]);
        __syncthreads();
        int o = tid;
        const float* wr = W_ph + o * 512;
        float acc = b_ph[o];
#pragma unroll 8
        for (int k = 0; k < 512; ++k) acc += hsp[k] * wr[k];
        out[row * 256 + o] = acc;
    }
}

extern "C" void kernel_launch(void* const* d_in, const int* in_sizes, int n_in,
                              void* d_out, int out_size) {
    (void)in_sizes; (void)n_in; (void)out_size;
    const float* x    = (const float*)d_in[0];
    const float* W_ix = (const float*)d_in[1];
    const float* W_fx = (const float*)d_in[2];
    const float* W_ox = (const float*)d_in[3];
    const float* W_gx = (const float*)d_in[4];
    const float* W_ih = (const float*)d_in[5];
    const float* b_ih = (const float*)d_in[6];
    const float* W_fh = (const float*)d_in[7];
    const float* b_fh = (const float*)d_in[8];
    const float* W_oh = (const float*)d_in[9];
    const float* b_oh = (const float*)d_in[10];
    const float* W_gh = (const float*)d_in[11];
    const float* b_gh = (const float*)d_in[12];
    const float* W_ph = (const float*)d_in[13];
    const float* b_ph = (const float*)d_in[14];

    cudaFuncSetAttribute(lstm_all, cudaFuncAttributeMaxDynamicSharedMemorySize, SMEM_BYTES);
    lstm_all<<<NCTA, TB, SMEM_BYTES>>>(x, W_ix, W_fx, W_ox, W_gx,
                                       W_ih, b_ih, W_fh, b_fh, W_oh, b_oh, W_gh, b_gh,
                                       W_ph, b_ph, (float*)d_out);
}